// round 17
// baseline (speedup 1.0000x reference)
#include <cuda_runtime.h>
#include <cuda_bf16.h>

// Problem constants (from reference: N=100000, E=1600000, D=64)
#define MAX_N 100000
#define D 64
#define CAP 64   // per-node edge-list capacity; deg ~ Poisson(16), P(>64) ~ 1e-20
#define BM 64
#define GPERS 296   // persistent grid: 148 SMs x 2 blocks

// Scratch (__device__ globals; no allocs allowed).
// g_cnt is zero-initialized at module load; whoever gathers a tile resets its
// counters in a post-loop store burst, so every launch starts from all-zero.
__device__ int g_slot[MAX_N * CAP];                     // 25.6 MB
__device__ int g_cnt[MAX_N];                            // 400 KB

// Consumer-group barrier (warps 0-3 only; id 0 is __syncthreads)
#define CBAR() asm volatile("bar.sync 1, 128;" ::: "memory")

// ---------------------------------------------------------------------------
// K1: build per-dst edge lists. One thread per edge (scalar beat the int4
// 4-edge variant: more TLP, no issue-serialized atomic chains).
// edge_index is int32: [0..E) = src, [E..2E) = dst.
// ---------------------------------------------------------------------------
__global__ void build_kernel(const int* __restrict__ ei, int E) {
    int e = blockIdx.x * blockDim.x + threadIdx.x;
    if (e >= E) return;
    int src = ei[e];
    int dst = ei[E + e];
    int pos = atomicAdd(&g_cnt[dst], 1);
    if (pos < CAP) g_slot[dst * CAP + pos] = src;
}

// ---------------------------------------------------------------------------
// Gather RPG rows per 16-lane group into sA (lane c owns float4 chunk c).
// sA[r] = (1+eps)*x[node] + sum_{src in list(node)} x[src]
// NO stores inside the load loop (R15 lesson). Counter clean is a separate
// post-loop burst by lane 0 of the owning group: the group's deg read is a
// single warp-wide LDG that precedes the store in warp program order.
// ---------------------------------------------------------------------------
template <int RPG>
__device__ __forceinline__ void gather_rows(const float* __restrict__ x,
                                            float s, int row_base, int N,
                                            int grp, int c, float* sA) {
    #pragma unroll
    for (int it = 0; it < RPG; it++) {
        int r = grp * RPG + it;
        int node = row_base + r;
        float4 acc = make_float4(0.f, 0.f, 0.f, 0.f);
        if (node < N) {
            acc = reinterpret_cast<const float4*>(x + (size_t)node * D)[c];
            acc.x *= s; acc.y *= s; acc.z *= s; acc.w *= s;
            int deg = __ldg(&g_cnt[node]);
            if (deg > CAP) deg = CAP;
            const int* sl = g_slot + (size_t)node * CAP;
            #pragma unroll 4
            for (int p = 0; p < deg; p++) {
                int src = __ldg(&sl[p]);
                float4 v = reinterpret_cast<const float4*>(
                               x + (size_t)src * D)[c];
                acc.x += v.x; acc.y += v.y; acc.z += v.z; acc.w += v.w;
            }
        }
        *reinterpret_cast<float4*>(&sA[r * D + c * 4]) = acc;
    }
    // post-loop counter clean (outside all load loops)
    if (c == 0) {
        #pragma unroll
        for (int it = 0; it < RPG; it++) {
            int node = row_base + grp * RPG + it;
            if (node < N) g_cnt[node] = 0;
        }
    }
}

// ---------------------------------------------------------------------------
// 4x4 micro-tile GEMM accumulate: acc[r][j] = sum_k sAm[i0+r][k]*sW[k][j0+j]
// ---------------------------------------------------------------------------
__device__ __forceinline__ void mm4x4(const float* sAm, const float* sW,
                                      int i0, int j0, float4 acc[4]) {
    #pragma unroll
    for (int r = 0; r < 4; r++) acc[r] = make_float4(0.f, 0.f, 0.f, 0.f);
    #pragma unroll
    for (int k0 = 0; k0 < D; k0 += 4) {
        float4 aF[4], bF[4];
        #pragma unroll
        for (int r = 0; r < 4; r++)
            aF[r] = *reinterpret_cast<const float4*>(&sAm[(i0 + r) * D + k0]);
        #pragma unroll
        for (int kk = 0; kk < 4; kk++)
            bF[kk] = *reinterpret_cast<const float4*>(&sW[(k0 + kk) * D + j0]);
        #pragma unroll
        for (int r = 0; r < 4; r++) {
            acc[r].x = fmaf(aF[r].x, bF[0].x, acc[r].x);
            acc[r].y = fmaf(aF[r].x, bF[0].y, acc[r].y);
            acc[r].z = fmaf(aF[r].x, bF[0].z, acc[r].z);
            acc[r].w = fmaf(aF[r].x, bF[0].w, acc[r].w);
            acc[r].x = fmaf(aF[r].y, bF[1].x, acc[r].x);
            acc[r].y = fmaf(aF[r].y, bF[1].y, acc[r].y);
            acc[r].z = fmaf(aF[r].y, bF[1].z, acc[r].z);
            acc[r].w = fmaf(aF[r].y, bF[1].w, acc[r].w);
            acc[r].x = fmaf(aF[r].z, bF[2].x, acc[r].x);
            acc[r].y = fmaf(aF[r].z, bF[2].y, acc[r].y);
            acc[r].z = fmaf(aF[r].z, bF[2].z, acc[r].z);
            acc[r].w = fmaf(aF[r].z, bF[2].w, acc[r].w);
            acc[r].x = fmaf(aF[r].w, bF[3].x, acc[r].x);
            acc[r].y = fmaf(aF[r].w, bF[3].y, acc[r].y);
            acc[r].z = fmaf(aF[r].w, bF[3].z, acc[r].z);
            acc[r].w = fmaf(aF[r].w, bF[3].w, acc[r].w);
        }
    }
}

// ---------------------------------------------------------------------------
// K2: persistent warp-specialized FUSED gather + MLP.
// Warps 0-3 (consumers): GEMM tile t from buffer buf.
// Warps 4-7 (producers): gather tile t+G into buffer buf^1 CONCURRENTLY.
// One __syncthreads per iteration swaps buffers. Consumers process the
// 64x64 tile as two 32-row halves (A rows 0-31, B rows 32-63) to keep
// 16 accumulators live. H tile reuses the A buffer:
//   L1-A -> CBAR -> write H-A (rows 0-31; L1-B reads rows 32-63, disjoint)
//   L1-B -> CBAR -> write H-B -> CBAR -> L2-A, L2-B -> STG.
// Dynamic smem 64KB: 2 x 16KB A-buffers + 32KB weights. 2 blocks/SM.
// ---------------------------------------------------------------------------
__global__ void __launch_bounds__(256, 2)
fused_mlp_kernel(const float* __restrict__ x, const float* __restrict__ eps,
                 const float* __restrict__ W1, const float* __restrict__ b1,
                 const float* __restrict__ W2, const float* __restrict__ b2,
                 float* __restrict__ out, int N, int T) {
    extern __shared__ float smem[];
    float* sW1 = smem + 2 * BM * D;
    float* sW2 = sW1 + D * D;

    int tid = threadIdx.x;

    // Stage weights once per persistent block (float4, coalesced, all threads)
    {
        const float4* w1v = reinterpret_cast<const float4*>(W1);
        const float4* w2v = reinterpret_cast<const float4*>(W2);
        float4* s1v = reinterpret_cast<float4*>(sW1);
        float4* s2v = reinterpret_cast<float4*>(sW2);
        #pragma unroll
        for (int q = 0; q < 4; q++) {
            s1v[tid + q * 256] = w1v[tid + q * 256];
            s2v[tid + q * 256] = w2v[tid + q * 256];
        }
    }

    float s = 1.0f + __ldg(eps);
    int j0 = (tid & 15) * 4;
    float4 b1v = __ldg(reinterpret_cast<const float4*>(b1 + j0));
    float4 b2v = __ldg(reinterpret_cast<const float4*>(b2 + j0));

    int t = blockIdx.x;

    // Prologue: ALL 8 warps gather first tile into buffer 0 (16 groups x 4)
    gather_rows<4>(x, s, t * BM, N, tid >> 4, tid & 15, smem);
    __syncthreads();
    int buf = 0;

    while (true) {
        int next = t + gridDim.x;

        if (tid < 128) {
            // ---------------- consumers: GEMM tile t ----------------
            float* sA = smem + buf * BM * D;
            int row_base = t * BM;
            int ty = tid >> 4;            // 0..7
            int iA = ty * 4;              // rows 0-31
            int iB = 32 + ty * 4;         // rows 32-63
            float4 acc[4];

            // Layer 1, half A
            mm4x4(sA, sW1, iA, j0, acc);
            CBAR();                        // all L1-A reads of rows 0-31 done
            #pragma unroll
            for (int r = 0; r < 4; r++) {
                float4 h;
                h.x = fmaxf(acc[r].x + b1v.x, 0.f);
                h.y = fmaxf(acc[r].y + b1v.y, 0.f);
                h.z = fmaxf(acc[r].z + b1v.z, 0.f);
                h.w = fmaxf(acc[r].w + b1v.w, 0.f);
                *reinterpret_cast<float4*>(&sA[(iA + r) * D + j0]) = h;
            }

            // Layer 1, half B (reads rows 32-63 only — disjoint from H-A)
            mm4x4(sA, sW1, iB, j0, acc);
            CBAR();                        // all L1-B reads of rows 32-63 done
            #pragma unroll
            for (int r = 0; r < 4; r++) {
                float4 h;
                h.x = fmaxf(acc[r].x + b1v.x, 0.f);
                h.y = fmaxf(acc[r].y + b1v.y, 0.f);
                h.z = fmaxf(acc[r].z + b1v.z, 0.f);
                h.w = fmaxf(acc[r].w + b1v.w, 0.f);
                *reinterpret_cast<float4*>(&sA[(iB + r) * D + j0]) = h;
            }
            CBAR();                        // full H visible

            // Layer 2, half A
            mm4x4(sA, sW2, iA, j0, acc);
            #pragma unroll
            for (int r = 0; r < 4; r++) {
                int grow = row_base + iA + r;
                if (grow < N) {
                    float4 o;
                    o.x = acc[r].x + b2v.x;
                    o.y = acc[r].y + b2v.y;
                    o.z = acc[r].z + b2v.z;
                    o.w = acc[r].w + b2v.w;
                    *reinterpret_cast<float4*>(out + (size_t)grow * D + j0) = o;
                }
            }
            // Layer 2, half B
            mm4x4(sA, sW2, iB, j0, acc);
            #pragma unroll
            for (int r = 0; r < 4; r++) {
                int grow = row_base + iB + r;
                if (grow < N) {
                    float4 o;
                    o.x = acc[r].x + b2v.x;
                    o.y = acc[r].y + b2v.y;
                    o.z = acc[r].z + b2v.z;
                    o.w = acc[r].w + b2v.w;
                    *reinterpret_cast<float4*>(out + (size_t)grow * D + j0) = o;
                }
            }
        } else {
            // ---------------- producers: gather tile t+G ----------------
            if (next < T) {
                int ptid = tid - 128;
                gather_rows<8>(x, s, next * BM, N, ptid >> 4, ptid & 15,
                               smem + (buf ^ 1) * BM * D);
            }
        }

        __syncthreads();                  // iteration boundary: swap buffers
        if (next >= T) break;
        t = next;
        buf ^= 1;
    }
}

// ---------------------------------------------------------------------------
// Launch: build -> persistent fused (single stream, graph-capturable).
// Input order per metadata: x, edge_index, W1, b1, W2, b2, eps
// ---------------------------------------------------------------------------
extern "C" void kernel_launch(void* const* d_in, const int* in_sizes, int n_in,
                              void* d_out, int out_size) {
    const float* x   = (const float*)d_in[0];
    const int*   ei  = (const int*)d_in[1];     // int32 (JAX x64 disabled)
    const float* W1  = (const float*)d_in[2];
    const float* b1  = (const float*)d_in[3];
    const float* W2  = (const float*)d_in[4];
    const float* b2  = (const float*)d_in[5];
    const float* eps = (const float*)d_in[6];
    float*       out = (float*)d_out;

    int N = in_sizes[0] / D;       // 100000
    int E = in_sizes[1] / 2;       // 1600000

    // K1: build per-dst edge lists (scalar)
    build_kernel<<<(E + 255) / 256, 256>>>(ei, E);

    // K2: persistent warp-specialized fused gather + MLP
    static const int SMEM_BYTES = (2 * BM * D + 2 * D * D) * (int)sizeof(float);
    cudaFuncSetAttribute(fused_mlp_kernel,
                         cudaFuncAttributeMaxDynamicSharedMemorySize,
                         SMEM_BYTES);
    int T = (N + BM - 1) / BM;     // 1563 tiles
    int G = GPERS < T ? GPERS : T;
    fused_mlp_kernel<<<G, 256, SMEM_BYTES>>>(x, eps, W1, b1, W2, b2,
                                             out, N, T);
}